// round 17
// baseline (speedup 1.0000x reference)
#include <cuda_runtime.h>
#include <math.h>

#define NCTA 128
#define NTHR 512
// smem: wfS 24576 float2 (192KB) | R4 768 float4 (12KB) | ghS 768 float4 (12KB)
#define SMEM_BYTES (196608 + 12288 + 12288)   // 221184

typedef unsigned long long u64;
typedef ulonglong2 ull2;
typedef unsigned int uint32;

__device__ __forceinline__ u64 fma2(u64 a, u64 b, u64 c) {
    u64 d;
    asm("fma.rn.f32x2 %0, %1, %2, %3;" : "=l"(d) : "l"(a), "l"(b), "l"(c));
    return d;
}
__device__ __forceinline__ float hsum(u64 v) {
    union { u64 u; float f[2]; } x; x.u = v;
    return x.f[0] + x.f[1];
}
__device__ __forceinline__ float sigm(float x) { return 1.f / (1.f + expf(-x)); }
__device__ __forceinline__ float softplusf(float x) {
    return fmaxf(x, 0.f) + log1pf(expf(-fabsf(x)));
}
__device__ __forceinline__ float tf32r(float x) {
    float r;
    asm("cvt.rna.tf32.f32 %0, %1;" : "=f"(r) : "f"(x));
    return r;
}
__device__ __forceinline__ void mma8(float* d, float4 av, float2 bv) {
    uint32 a0 = __float_as_uint(av.x), a1 = __float_as_uint(av.y);
    uint32 a2 = __float_as_uint(av.z), a3 = __float_as_uint(av.w);
    uint32 b0 = __float_as_uint(bv.x), b1 = __float_as_uint(bv.y);
    asm volatile(
        "mma.sync.aligned.m16n8k8.row.col.f32.tf32.tf32.f32 "
        "{%0,%1,%2,%3}, {%4,%5,%6,%7}, {%8,%9}, {%0,%1,%2,%3};"
        : "+f"(d[0]), "+f"(d[1]), "+f"(d[2]), "+f"(d[3])
        : "r"(a0), "r"(a1), "r"(a2), "r"(a3), "r"(b0), "r"(b1));
}

// ---------------- persistent state ----------------
__device__ float g_det[2][64 * 1024];
__device__ float g_detf[2][64 * 1024];       // tf32 fragment-packed deter
__device__ float g_embf[64 * 1024];          // tf32 fragment-packed emb
__device__ float g_h1[64 * 512];
__device__ float g_hq[64 * 512];
__device__ float g_stoch[64 * 32];
__device__ float g_obsq[64 * 256 * 512];
__device__ float g_actemb[64 * 256 * 1024];
__device__ float2 g_w1frag[128 * 4096];
__device__ unsigned g_leaf[8][32];
__device__ unsigned g_root;
__device__ volatile unsigned g_gen;

__device__ __forceinline__ void gbar() {
    __syncthreads();
    if (threadIdx.x == 0) {
        __threadfence();
        unsigned gen = g_gen;
        int l = blockIdx.x & 7;
        if (atomicAdd(&g_leaf[l][0], 1u) == 15) {
            g_leaf[l][0] = 0;
            __threadfence();
            if (atomicAdd(&g_root, 1u) == 7) {
                g_root = 0;
                __threadfence();
                g_gen = gen + 1;
            }
        }
        while (g_gen == gen) { }
        __threadfence();
    }
    __syncthreads();
}

__device__ __forceinline__ int fragIdx(int row, int k) {
    int k8 = k >> 3, rb = row >> 4, rp = row & 15;
    int lane = (rp & 7) * 4 + (k & 3);
    int reg  = ((rp >> 3) & 1) + (((k & 7) >> 2) << 1);
    return ((k8 * 4 + rb) * 32 + lane) * 4 + reg;
}

// ======== pre-pass A: g_obsq ========
__global__ void __launch_bounds__(256)
obsq_kernel(const float* __restrict__ obs, const float* __restrict__ Wq1,
            const float* __restrict__ bq1) {
    extern __shared__ float4 S[];
    const int tid = threadIdx.x, lane = tid & 31, wrp = tid >> 5;
    const int rt = blockIdx.x >> 2, ct = blockIdx.x & 3;
    const int r0 = rt * 64, c0 = ct * 128;
    const int rh = wrp >> 2, cgq = wrp & 3;

    u64 acc[32];
    #pragma unroll
    for (int j = 0; j < 32; ++j) acc[j] = 0ull;

    for (int c = 0; c < 16; ++c) {
        for (int i = tid; i < 1024; i += 256) {
            int row = i >> 4, k4 = i & 15;
            S[row * 17 + k4] = *(const float4*)(obs + (size_t)(r0 + row) * 1024 + c * 64 + k4 * 4);
        }
        for (int i = tid; i < 2048; i += 256) {
            int col = i >> 4, k4 = i & 15;
            S[1088 + col * 16 + k4] =
                *(const float4*)(Wq1 + (size_t)(c0 + col) * 2048 + 1024 + c * 64 + k4 * 4);
        }
        __syncthreads();
        const ull2* xr = (const ull2*)(S + (rh * 32 + lane) * 17);
        const ull2* wb = (const ull2*)(S + 1088 + (cgq * 32) * 16);
        for (int k4 = 0; k4 < 16; ++k4) {
            ull2 x = xr[k4];
            #pragma unroll
            for (int j = 0; j < 32; ++j) {
                ull2 w = wb[j * 16 + k4];
                acc[j] = fma2(w.x, x.x, acc[j]);
                acc[j] = fma2(w.y, x.y, acc[j]);
            }
        }
        __syncthreads();
    }
    int r = r0 + rh * 32 + lane;
    #pragma unroll
    for (int j = 0; j < 32; ++j) {
        int col = c0 + cgq * 32 + j;
        g_obsq[(size_t)r * 512 + col] = hsum(acc[j]) + bq1[col];
    }
}

// ======== pre-pass B: g_actemb ========
__global__ void __launch_bounds__(256)
actemb_kernel(const float* __restrict__ act, const float* __restrict__ Wsa,
              const float* __restrict__ bsa) {
    extern __shared__ float4 S[];
    const int tid = threadIdx.x, lane = tid & 31, wrp = tid >> 5;
    const int rt = blockIdx.x >> 3, ct = blockIdx.x & 7;
    const int r0 = rt * 64, c0 = ct * 128;
    const int rh = wrp >> 2, cgq = wrp & 3;

    for (int i = tid; i < 1024; i += 256) {
        int row = i >> 4, k4 = i & 15;
        S[row * 17 + k4] = *(const float4*)(act + (size_t)(r0 + row) * 64 + k4 * 4);
    }
    for (int i = tid; i < 2048; i += 256) {
        int col = i >> 4, k4 = i & 15;
        S[1088 + col * 16 + k4] =
            *(const float4*)(Wsa + (size_t)(c0 + col) * 96 + 32 + k4 * 4);
    }
    __syncthreads();

    u64 acc[32];
    #pragma unroll
    for (int j = 0; j < 32; ++j) acc[j] = 0ull;
    const ull2* xr = (const ull2*)(S + (rh * 32 + lane) * 17);
    const ull2* wb = (const ull2*)(S + 1088 + (cgq * 32) * 16);
    for (int k4 = 0; k4 < 16; ++k4) {
        ull2 x = xr[k4];
        #pragma unroll
        for (int j = 0; j < 32; ++j) {
            ull2 w = wb[j * 16 + k4];
            acc[j] = fma2(w.x, x.x, acc[j]);
            acc[j] = fma2(w.y, x.y, acc[j]);
        }
    }
    int r = r0 + rh * 32 + lane;
    #pragma unroll
    for (int j = 0; j < 32; ++j) {
        int col = c0 + cgq * 32 + j;
        g_actemb[(size_t)r * 1024 + col] = hsum(acc[j]) + bsa[col];
    }
}

// ======== persistent rollout ========
__global__ void __launch_bounds__(NTHR, 1)
rssm_kernel(const float* __restrict__ obs,   const float* __restrict__ act,
            const float* __restrict__ nzp,   const float* __restrict__ nzq,
            const float* __restrict__ Wsa, const float* __restrict__ bsa,
            const float* __restrict__ Wih, const float* __restrict__ bih,
            const float* __restrict__ Whh, const float* __restrict__ bhh,
            const float* __restrict__ Wp1, const float* __restrict__ bp1,
            const float* __restrict__ Wp2, const float* __restrict__ bp2,
            const float* __restrict__ Wq1, const float* __restrict__ bq1,
            const float* __restrict__ Wq2, const float* __restrict__ bq2,
            float* __restrict__ out)
{
    extern __shared__ char SM[];
    float2* wfS = (float2*)SM;                 // GRU weight frags (cth0: i, cth1: h)
    float4* R4  = (float4*)(SM + 196608);      // 768 f4: ph1 staging / i-dump / ph3 dump
    float*  Rf  = (float*)R4;
    float4* GH4 = (float4*)(SM + 196608 + 12288);  // 768 f4: gh partial tiles
    float*  GHf = (float*)GH4;

    const int tid  = threadIdx.x;
    const int lane = tid & 31;
    const int wrp  = tid >> 5;
    const int c0g  = blockIdx.x * 8;
    // ph3 warp ids
    const int rb3  = wrp & 3;
    const int ks3  = wrp >> 2;
    // head assignment
    const bool isQ = blockIdx.x & 1;
    const int  c0  = (blockIdx.x >> 1) * 8;
    const float* W1 = isQ ? Wq1 : Wp1;
    const size_t K1 = isQ ? 2048 : 1024;

    // ---- init ----
    for (int i = blockIdx.x * NTHR + tid; i < 64 * 1024; i += NCTA * NTHR) {
        g_det[0][i]  = 0.f;
        g_detf[0][i] = 0.f;
    }
    for (int i = blockIdx.x * NTHR + tid; i < 64 * 32; i += NCTA * NTHR)
        g_stoch[i] = 0.f;
    for (int i = tid; i < 24576; i += NTHR) {
        int ct = i >> 12, k8 = (i >> 5) & 127, ln = i & 31;
        int g = ct % 3, cm = ct / 3;
        int n = ln >> 2, kl = ln & 3;
        const float* Wm = cm ? Whh : Wih;
        size_t rowo = ((size_t)(g * 1024 + c0g + n)) * 1024 + k8 * 8 + kl;
        wfS[i] = make_float2(tf32r(Wm[rowo]), tf32r(Wm[rowo + 4]));
    }
    for (int i = tid; i < 4096; i += NTHR) {
        int k8 = i >> 5, ln = i & 31;
        int n = ln >> 2, kl = ln & 3;
        size_t rowo = (size_t)(c0 + n) * K1 + k8 * 8 + kl;
        g_w1frag[blockIdx.x * 4096 + i] =
            make_float2(tf32r(W1[rowo]), tf32r(W1[rowo + 4]));
    }
    gbar();

    for (int t = 0; t < 256; ++t) {
        const int p = t & 1;
        const float* detP = g_det[p];
        float*       detN = g_det[p ^ 1];

        // ===== phase A: emb (warps 0-7) ∥ h-gate GEMM on detf(t-1) (warps 8-15) =====
        if (wrp < 8) {
            float4* stS = R4;           // 64 x 9 f4
            float4* wS1 = R4 + 600;     // 8 x 9 f4 (fits: 600+72=672<=768)
            for (int i = tid; i < 512; i += 256) {
                int row = i >> 3, k4 = i & 7;
                stS[row * 9 + k4] = *(const float4*)(g_stoch + row * 32 + k4 * 4);
            }
            if (tid < 64) {
                int c = tid >> 3, k4 = tid & 7;
                wS1[c * 9 + k4] = *(const float4*)(Wsa + (size_t)(c0g + c) * 96 + k4 * 4);
            }
            asm volatile("bar.sync 1, 256;" ::: "memory");
            int pr = wrp * 8 + (lane & 7);
            int cq1 = lane >> 3;
            u64 a0 = 0, a1 = 0;
            #pragma unroll
            for (int k4 = 0; k4 < 8; ++k4) {
                ull2 x  = *(const ull2*)(stS + pr * 9 + k4);
                ull2 w0 = *(const ull2*)(wS1 + cq1 * 9 + k4);
                ull2 w1 = *(const ull2*)(wS1 + (cq1 + 4) * 9 + k4);
                a0 = fma2(w0.x, x.x, a0); a0 = fma2(w0.y, x.y, a0);
                a1 = fma2(w1.x, x.x, a1); a1 = fma2(w1.y, x.y, a1);
            }
            int colA = c0g + cq1, colB = colA + 4;
            float bA = g_actemb[((size_t)pr * 256 + t) * 1024 + colA];
            float bB = g_actemb[((size_t)pr * 256 + t) * 1024 + colB];
            g_embf[fragIdx(pr, colA)] = tf32r(fmaxf(hsum(a0) + bA, 0.f));
            g_embf[fragIdx(pr, colB)] = tf32r(fmaxf(hsum(a1) + bB, 0.f));
        } else {
            const int wh = wrp - 8;
            const int rb = wh & 3, ks = wh >> 2;
            const float* Af = g_detf[p];
            const float2* wf = wfS + 3 * 4096;   // h-gate (cth=1) block
            float acc[3][4];
            #pragma unroll
            for (int g = 0; g < 3; ++g)
                #pragma unroll
                for (int e = 0; e < 4; ++e) acc[g][e] = 0.f;
            #pragma unroll 4
            for (int q = 0; q < 64; ++q) {
                int k8 = ks * 64 + q;
                float4 av = *(const float4*)(Af + ((size_t)(k8 * 4 + rb) * 32 + lane) * 4);
                #pragma unroll
                for (int g = 0; g < 3; ++g) {
                    float2 bv = wf[g * 4096 + k8 * 32 + lane];
                    mma8(acc[g], av, bv);
                }
            }
            #pragma unroll
            for (int g = 0; g < 3; ++g)
                GH4[((rb * 2 + ks) * 3 + g) * 32 + lane] =
                    make_float4(acc[g][0], acc[g][1], acc[g][2], acc[g][3]);
        }
        gbar();

        // ===== phase B: i-gate GEMM (warps 0-7) + gate math (all) =====
        if (wrp < 8) {
            const int rb = wrp & 3, ks = wrp >> 2;
            const float* Af = g_embf;
            float acc[3][4];
            #pragma unroll
            for (int g = 0; g < 3; ++g)
                #pragma unroll
                for (int e = 0; e < 4; ++e) acc[g][e] = 0.f;
            #pragma unroll 4
            for (int q = 0; q < 64; ++q) {
                int k8 = ks * 64 + q;
                float4 av = *(const float4*)(Af + ((size_t)(k8 * 4 + rb) * 32 + lane) * 4);
                #pragma unroll
                for (int g = 0; g < 3; ++g) {
                    float2 bv = wfS[g * 4096 + k8 * 32 + lane];
                    mma8(acc[g], av, bv);
                }
            }
            #pragma unroll
            for (int g = 0; g < 3; ++g)
                R4[((rb * 2 + ks) * 3 + g) * 32 + lane] =
                    make_float4(acc[g][0], acc[g][1], acc[g][2], acc[g][3]);
        }
        __syncthreads();
        {
            int row = tid >> 3, coll = tid & 7, col = c0g + coll;
            int rbw = row >> 4, rp = row & 15;
            int lanew = (rp & 7) * 4 + (coll >> 1);
            int comp  = (coll & 1) + ((rp >> 3) << 1);
            float gi[3], gh[3];
            #pragma unroll
            for (int g = 0; g < 3; ++g) {
                int i0 = (((rbw * 2 + 0) * 3 + g) * 32 + lanew) * 4 + comp;
                int i1 = (((rbw * 2 + 1) * 3 + g) * 32 + lanew) * 4 + comp;
                gi[g] = Rf[i0] + Rf[i1] + bih[col + 1024 * g];
                gh[g] = GHf[i0] + GHf[i1] + bhh[col + 1024 * g];
            }
            float r = sigm(gi[0] + gh[0]);
            float z = sigm(gi[1] + gh[1]);
            float n = tanhf(gi[2] + r * gh[2]);
            float hp = detP[(size_t)row * 1024 + col];
            float hw = (1.f - z) * n + z * hp;
            detN[(size_t)row * 1024 + col] = hw;
            out[((size_t)row * 256 + t) * 1216 + col] = hw;
            g_detf[p ^ 1][fragIdx(row, col)] = tf32r(hw);
        }
        gbar();

        // ===== phase C: h1/hq first layer via tf32 mma (16 warps) =====
        {
            const float* Df = g_detf[p ^ 1];
            const float2* w1f = g_w1frag + blockIdx.x * 4096;
            float acc[4] = {0.f, 0.f, 0.f, 0.f};
            #pragma unroll 4
            for (int q = 0; q < 32; ++q) {
                int k8 = ks3 * 32 + q;
                float4 av = *(const float4*)(Df + ((size_t)(k8 * 4 + rb3) * 32 + lane) * 4);
                float2 bv = w1f[k8 * 32 + lane];
                mma8(acc, av, bv);
            }
            if (ks3 > 0)
                R4[(rb3 * 3 + (ks3 - 1)) * 32 + lane] =
                    make_float4(acc[0], acc[1], acc[2], acc[3]);
            __syncthreads();
            if (ks3 == 0) {
                #pragma unroll
                for (int s = 0; s < 3; ++s) {
                    float4 v = R4[(rb3 * 3 + s) * 32 + lane];
                    acc[0] += v.x; acc[1] += v.y; acc[2] += v.z; acc[3] += v.w;
                }
                float* dst = isQ ? g_hq : g_h1;
                int rbase = rb3 * 16 + (lane >> 2);
                int n0 = (lane & 3) * 2;
                #pragma unroll
                for (int e = 0; e < 4; ++e) {
                    int row = rbase + ((e >> 1) << 3);
                    int col = c0 + n0 + (e & 1);
                    float base = isQ ? g_obsq[((size_t)row * 256 + t) * 512 + col]
                                     : bp1[col];
                    dst[(size_t)row * 512 + col] = fmaxf(acc[e] + base, 0.f);
                }
            }
        }
        gbar();

        // ===== phase D: heads (fp32) =====
        {
            const int gw = blockIdx.x * 16 + wrp;
            #pragma unroll
            for (int i = 0; i < 2; ++i) {
                int pi    = gw * 2 + i;
                int which = pi & 1;
                int s     = (pi >> 1) & 31;
                int bb    = pi >> 6;
                const float* hv = (which ? g_hq : g_h1) + (size_t)bb * 512;
                const float* W2 = which ? Wq2 : Wp2;
                u64 am = 0, asd = 0;
                #pragma unroll
                for (int q = 0; q < 4; ++q) {
                    float4 xf = __ldcg((const float4*)(hv + lane * 16 + q * 4));
                    ull2 x = *(ull2*)&xf;
                    ull2 u = *(const ull2*)(W2 + (size_t)s * 512 + lane * 16 + q * 4);
                    ull2 v = *(const ull2*)(W2 + (size_t)(s + 32) * 512 + lane * 16 + q * 4);
                    am  = fma2(u.x, x.x, am);  am  = fma2(u.y, x.y, am);
                    asd = fma2(v.x, x.x, asd); asd = fma2(v.y, x.y, asd);
                }
                float sm = hsum(am), ss = hsum(asd);
                #pragma unroll
                for (int o = 16; o; o >>= 1) {
                    sm += __shfl_xor_sync(0xffffffffu, sm, o);
                    ss += __shfl_xor_sync(0xffffffffu, ss, o);
                }
                if (lane == 0) {
                    const float* b2 = which ? bq2 : bp2;
                    float mean = sm + b2[s];
                    float stdv = softplusf(ss + b2[s + 32]) + 1e-5f;
                    const float* nz = which ? nzq : nzp;
                    float e  = nz[((size_t)bb * 256 + t) * 32 + s];
                    float st = mean + stdv * e;
                    size_t base = ((size_t)bb * 256 + t) * 1216 + 1024 + which * 96;
                    out[base + s]      = mean;
                    out[base + 32 + s] = stdv;
                    out[base + 64 + s] = st;
                    if (which) g_stoch[bb * 32 + s] = st;
                }
            }
        }
        gbar();
    }
}

extern "C" void kernel_launch(void* const* d_in, const int* in_sizes, int n_in,
                              void* d_out, int out_size) {
    (void)in_sizes; (void)n_in; (void)out_size;
    cudaFuncSetAttribute((const void*)obsq_kernel,
                         cudaFuncAttributeMaxDynamicSharedMemorySize, 50176);
    cudaFuncSetAttribute((const void*)actemb_kernel,
                         cudaFuncAttributeMaxDynamicSharedMemorySize, 50176);
    cudaFuncSetAttribute((const void*)rssm_kernel,
                         cudaFuncAttributeMaxDynamicSharedMemorySize, SMEM_BYTES);
    actemb_kernel<<<2048, 256, 50176>>>(
        (const float*)d_in[1], (const float*)d_in[4], (const float*)d_in[5]);
    obsq_kernel<<<1024, 256, 50176>>>(
        (const float*)d_in[0], (const float*)d_in[14], (const float*)d_in[15]);
    rssm_kernel<<<NCTA, NTHR, SMEM_BYTES>>>(
        (const float*)d_in[0],  (const float*)d_in[1],
        (const float*)d_in[2],  (const float*)d_in[3],
        (const float*)d_in[4],  (const float*)d_in[5],
        (const float*)d_in[6],  (const float*)d_in[7],
        (const float*)d_in[8],  (const float*)d_in[9],
        (const float*)d_in[10], (const float*)d_in[11],
        (const float*)d_in[12], (const float*)d_in[13],
        (const float*)d_in[14], (const float*)d_in[15],
        (const float*)d_in[16], (const float*)d_in[17],
        (float*)d_out);
}